// round 9
// baseline (speedup 1.0000x reference)
#include <cuda_runtime.h>
#include <cstdint>

// MaxUnpooling2D: updates [16,64,64,256] f32, mask [16,64,64,256] i32 (flat idx
// into [16,128,128,256]), out [16,128,128,256] f32.
//
// R9: GATHER formulation (scatter-side knobs exhausted at DRAM~71.7%).
// One thread per OUTPUT float4-group q: read the source cell's upd/mask and
// select; out[q] is the only store -> single perfectly-linear write stream
// chip-wide. Input reads are 4x redundant but:
//   - x-pair duplicate (x=2w,2w+1) is read by adjacent warps in the SAME
//     block -> L1 hit;
//   - y-pair duplicate is 32 blocks away -> concurrently in flight -> L2 hit.
// Unique DRAM reads stay ~128MB; selection test is just m.j == 4q+j.

namespace {
constexpr int NQ      = 16 * 128 * 128 * 64;   // 16,777,216 output f4-groups
constexpr int THREADS = 256;
constexpr int BLOCKS  = NQ / THREADS;          // 65536
}

__global__ void __launch_bounds__(THREADS, 8)
max_unpool_gather_kernel(const float4* __restrict__ upd,
                         const int4*  __restrict__ mask,
                         float4*      __restrict__ out)
{
    int q = blockIdx.x * THREADS + threadIdx.x;

    // q = ((b*128 + y)*128 + x)*64 + c4
    int c4 = q & 63;
    int x  = (q >> 6)  & 127;
    int y  = (q >> 13) & 127;
    int b  = q >> 20;

    // Source cell group: ((b*64 + y/2)*64 + x/2)*64 + c4
    int g = (((((b << 6) | (y >> 1)) << 6) | (x >> 1)) << 6) | c4;

    float4 v = upd[g];
    int4   m = mask[g];

    int o = q << 2;   // flat output element index of lane 0

    float4 r = make_float4(m.x == o     ? v.x : 0.f,
                           m.y == o + 1 ? v.y : 0.f,
                           m.z == o + 2 ? v.z : 0.f,
                           m.w == o + 3 ? v.w : 0.f);

    out[q] = r;
}

extern "C" void kernel_launch(void* const* d_in, const int* in_sizes, int n_in,
                              void* d_out, int out_size)
{
    const float4* upd  = reinterpret_cast<const float4*>(d_in[0]);
    const int4*   mask = reinterpret_cast<const int4*>(d_in[1]);
    float4*       out  = reinterpret_cast<float4*>(d_out);

    max_unpool_gather_kernel<<<BLOCKS, THREADS>>>(upd, mask, out);
}

// round 10
// speedup vs baseline: 1.1569x; 1.1569x over previous
#include <cuda_runtime.h>
#include <cstdint>

// MaxUnpooling2D: updates [16,64,64,256] f32, mask [16,64,64,256] i32 (flat idx
// into [16,128,128,256]), out [16,128,128,256] f32.
//
// Each pooled cell targets exactly one slot of its private 2x2 window -> no
// duplicates -> plain stores; zero-fill fused.
//
// R10 = R8 (row-split scatter; best measured: 59.07us kernel / 63.68us
// harness) x R5 (256-bit global accesses; neutral DRAM%, halves instr/byte).
// One thread = 8 consecutive channels of ONE window row (ry in {0,1}):
//   1x32B upd load + 1x32B mask load + 2x32B stores 1KB apart, single row.
// Per-warp: 2x1KB coalesced loads, 2x1KB single-row coalesced stores.
// Inputs read twice (sibling-row thread) but duplicates hit L1/L2 (measured
// in R8: DRAM reads unchanged).

namespace {
constexpr int ROW   = 2 * 64 * 256;       // 32768  (dy=1 stride in out)
constexpr int COLS  = 256;                // dx=1 stride in out
constexpr int IMG   = 2 * 64 * ROW;       // batch stride in out
constexpr int NT    = 16 * 64 * 64 * 2 * (256 / 8);  // 4,194,304 threads
constexpr int THREADS = 256;
constexpr int BLOCKS  = NT / THREADS;                // 16384
}

__device__ __forceinline__ void ldg256_f(const float* p, float* v)
{
    asm volatile(
        "ld.global.nc.v8.f32 {%0,%1,%2,%3,%4,%5,%6,%7}, [%8];"
        : "=f"(v[0]), "=f"(v[1]), "=f"(v[2]), "=f"(v[3]),
          "=f"(v[4]), "=f"(v[5]), "=f"(v[6]), "=f"(v[7])
        : "l"(p));
}

__device__ __forceinline__ void ldg256_i(const int* p, int* v)
{
    asm volatile(
        "ld.global.nc.v8.b32 {%0,%1,%2,%3,%4,%5,%6,%7}, [%8];"
        : "=r"(v[0]), "=r"(v[1]), "=r"(v[2]), "=r"(v[3]),
          "=r"(v[4]), "=r"(v[5]), "=r"(v[6]), "=r"(v[7])
        : "l"(p));
}

__device__ __forceinline__ void stg256_f(float* p, const float* v)
{
    asm volatile(
        "st.global.v8.f32 [%0], {%1,%2,%3,%4,%5,%6,%7,%8};"
        :: "l"(p),
           "f"(v[0]), "f"(v[1]), "f"(v[2]), "f"(v[3]),
           "f"(v[4]), "f"(v[5]), "f"(v[6]), "f"(v[7])
        : "memory");
}

__global__ void __launch_bounds__(THREADS, 8)
max_unpool_kernel(const float* __restrict__ upd,
                  const int*   __restrict__ mask,
                  float*       __restrict__ out)
{
    int t = blockIdx.x * THREADS + threadIdx.x;

    // t = (((b*64 + h)*64 + w)*2 + ry)*32 + c8
    int c8 = t & 31;
    int ry = (t >> 5) & 1;
    int w  = (t >> 6)  & 63;
    int h  = (t >> 12) & 63;
    int b  = t >> 18;

    // Input 8-group index: ((b*64+h)*64 + w)*32 + c8
    int g = ((t >> 6) << 5) | c8;

    // Window origin (2h, 2w) at channel 8*c8; this thread's row.
    int o00   = b * IMG + (h << 1) * ROW + (w << 1) * COLS + (c8 << 3);
    int sel   = ry * ROW;             // 0 or ROW
    int obase = o00 + sel;

    float v[8];
    int   m[8];
    ldg256_f(upd  + (size_t)g * 8, v);
    ldg256_i(mask + (size_t)g * 8, m);

    int d[8];
#pragma unroll
    for (int j = 0; j < 8; ++j)
        d[j] = m[j] - o00 - j;        // in {0, COLS, ROW, ROW+COLS}

    float r[8];

#pragma unroll
    for (int j = 0; j < 8; ++j) r[j] = (d[j] == sel) ? v[j] : 0.f;
    stg256_f(out + obase, r);

#pragma unroll
    for (int j = 0; j < 8; ++j) r[j] = (d[j] == sel + COLS) ? v[j] : 0.f;
    stg256_f(out + obase + COLS, r);
}

extern "C" void kernel_launch(void* const* d_in, const int* in_sizes, int n_in,
                              void* d_out, int out_size)
{
    const float* upd  = reinterpret_cast<const float*>(d_in[0]);
    const int*   mask = reinterpret_cast<const int*>(d_in[1]);
    float*       out  = reinterpret_cast<float*>(d_out);

    max_unpool_kernel<<<BLOCKS, THREADS>>>(upd, mask, out);
}